// round 3
// baseline (speedup 1.0000x reference)
#include <cuda_runtime.h>
#include <math.h>

// Problem dims
#define Bsz 256
#define Slen 128
#define Fdim 128
#define Hdim 512
#define Cdim 64
#define Ldim 16
#define G4  2048           // 4*H
#define KTOT 640           // H + F (fused [h | x_t] GEMM)
#define NCHUNK 20          // 640 / 32

#define APAD 19            // A smem row pad (conflict-free transposing STS)
#define BPAD 72            // B smem row pad

// Scratch (device globals; no allocations allowed)
__device__ float g_h[2][Bsz * Hdim];     // ping-pong hidden state
__device__ float g_c[Bsz * Hdim];        // cell state
__device__ float g_tmp[Bsz * Hdim];      // context-gate hidden
__device__ float g_ctx[Bsz * 3 * Hdim];  // sigmoid context gates [ci|cf|co]

__device__ __forceinline__ float sigmoidf(float x) {
    return 1.0f / (1.0f + expf(-x));
}

// ---------------------------------------------------------------------------
__global__ void zero_state_kernel() {
    int i = blockIdx.x * blockDim.x + threadIdx.x;
    if (i < Bsz * Hdim) {
        g_h[0][i] = 0.0f;
        g_c[i] = 0.0f;
    }
}

// ---------------------------------------------------------------------------
// Context gate stage 1: tmp = relu(context @ cg_w1 + cg_b1)   [256,512]
// ---------------------------------------------------------------------------
__global__ __launch_bounds__(128) void ctx1_kernel(
    const float* __restrict__ context,   // [256,64]
    const float* __restrict__ cg_w1,     // [64,512]
    const float* __restrict__ cg_b1)     // [512]
{
    __shared__ float cr[Cdim];
    int b = blockIdx.x;
    for (int k = threadIdx.x; k < Cdim; k += 128) cr[k] = context[b * Cdim + k];
    __syncthreads();
#pragma unroll
    for (int j = 0; j < 4; j++) {
        int n = threadIdx.x + j * 128;
        float s = cg_b1[n];
        for (int k = 0; k < Cdim; k++) s += cr[k] * cg_w1[k * Hdim + n];
        g_tmp[b * Hdim + n] = fmaxf(s, 0.0f);
    }
}

// ---------------------------------------------------------------------------
// Context gate stage 2: ctx = sigmoid(tmp @ cg_w2 + cg_b2)    [256,1536]
// ---------------------------------------------------------------------------
__global__ __launch_bounds__(256) void ctx2_kernel(
    const float* __restrict__ cg_w2,     // [512,1536]
    const float* __restrict__ cg_b2)     // [1536]
{
    __shared__ float tr[Hdim];
    int b = blockIdx.x;
    for (int k = threadIdx.x; k < Hdim; k += 256) tr[k] = g_tmp[b * Hdim + k];
    __syncthreads();
#pragma unroll
    for (int j = 0; j < 6; j++) {
        int n = threadIdx.x + j * 256;
        float s = cg_b2[n];
        for (int k = 0; k < Hdim; k++) s += tr[k] * cg_w2[k * 3 * Hdim + n];
        g_ctx[b * 3 * Hdim + n] = sigmoidf(s);
    }
}

// ---------------------------------------------------------------------------
// Fused LSTM step. CTA tile: 16 batch x (16 hcol x 4 gates). grid (32,16)=512.
// 128 threads; thread = 2 rows x 4 gates = 8 accumulators.
// K=640 in 20 chunks of 32, double-buffered smem, register-staged prefetch.
// A smem: [kk][row] pad APAD (conflict-free both sides).
// B smem: [kk][hc*4+g] pad BPAD (LDS.128 per thread yields 4 gate weights).
// ---------------------------------------------------------------------------
__device__ __forceinline__ void ldg_tiles(
    const float* __restrict__ h_in, const float* __restrict__ x,
    const float* __restrict__ W_hh, const float* __restrict__ W_ih,
    int t, int b0, int h0, int k0, int tid, float4& ra, float4 rb[4])
{
    // A: 16 rows x 32 kk = 128 float4; lane: q = tid&7 (k-quad), r = tid>>3 (row)
    const int q = tid & 7;
    const int r = tid >> 3;
    if (k0 < Hdim) {
        ra = *(const float4*)&h_in[(b0 + r) * Hdim + k0 + q * 4];
#pragma unroll
        for (int i = 0; i < 4; i++) {
            int idx = i * 128 + tid, kk = idx >> 4, f = idx & 15;
            int g = f >> 2, hq = f & 3;
            rb[i] = *(const float4*)&W_hh[(k0 + kk) * G4 + g * Hdim + h0 + hq * 4];
        }
    } else {
        int kx = k0 - Hdim;
        ra = *(const float4*)&x[((size_t)(b0 + r) * Slen + t) * Fdim + kx + q * 4];
#pragma unroll
        for (int i = 0; i < 4; i++) {
            int idx = i * 128 + tid, kk = idx >> 4, f = idx & 15;
            int g = f >> 2, hq = f & 3;
            rb[i] = *(const float4*)&W_ih[(kx + kk) * G4 + g * Hdim + h0 + hq * 4];
        }
    }
}

__device__ __forceinline__ void sts_tiles(
    float (*__restrict__ As)[APAD], float* __restrict__ Bs,
    int tid, const float4& ra, const float4 rb[4])
{
    const int q = tid & 7;
    const int r = tid >> 3;
    As[q * 4 + 0][r] = ra.x;
    As[q * 4 + 1][r] = ra.y;
    As[q * 4 + 2][r] = ra.z;
    As[q * 4 + 3][r] = ra.w;
#pragma unroll
    for (int i = 0; i < 4; i++) {
        int idx = i * 128 + tid, kk = idx >> 4, f = idx & 15;
        int g = f >> 2, hq = f & 3;
        float* brow = Bs + kk * BPAD;
        brow[(hq * 4 + 0) * 4 + g] = rb[i].x;
        brow[(hq * 4 + 1) * 4 + g] = rb[i].y;
        brow[(hq * 4 + 2) * 4 + g] = rb[i].z;
        brow[(hq * 4 + 3) * 4 + g] = rb[i].w;
    }
}

__global__ __launch_bounds__(128) void step_kernel(
    const float* __restrict__ x,      // [256,128,128]
    const float* __restrict__ W_ih,   // [128,2048]
    const float* __restrict__ b_ih,   // [2048]
    const float* __restrict__ W_hh,   // [512,2048]
    const float* __restrict__ b_hh,   // [2048]
    int t)
{
    __shared__ float As[2][32][APAD];
    __shared__ float Bs[2][32 * BPAD];

    const int tid = threadIdx.x;
    const int hc = tid & 15;          // h-column within tile
    const int r0 = (tid >> 4) * 2;    // 2 batch rows per thread
    const int h0 = blockIdx.x * 16;
    const int b0 = blockIdx.y * 16;

    const float* __restrict__ h_in = g_h[t & 1];
    float* __restrict__ h_out = g_h[(t + 1) & 1];

    float acc[2][4];
#pragma unroll
    for (int r = 0; r < 2; r++)
#pragma unroll
        for (int g = 0; g < 4; g++) acc[r][g] = 0.0f;

    float4 ra, rb[4];
    ldg_tiles(h_in, x, W_hh, W_ih, t, b0, h0, 0, tid, ra, rb);
    sts_tiles(As[0], Bs[0], tid, ra, rb);
    __syncthreads();

    for (int c = 0; c < NCHUNK; c++) {
        const int buf = c & 1;
        if (c + 1 < NCHUNK)
            ldg_tiles(h_in, x, W_hh, W_ih, t, b0, h0, (c + 1) * 32, tid, ra, rb);

        const float (*__restrict__ Asb)[APAD] = As[buf];
        const float* __restrict__ Bsb = Bs[buf];
#pragma unroll
        for (int kk = 0; kk < 32; kk++) {
            float4 bq = *(const float4*)&Bsb[kk * BPAD + hc * 4];
            float a0 = Asb[kk][r0 + 0];
            float a1 = Asb[kk][r0 + 1];
            acc[0][0] += a0 * bq.x; acc[0][1] += a0 * bq.y;
            acc[0][2] += a0 * bq.z; acc[0][3] += a0 * bq.w;
            acc[1][0] += a1 * bq.x; acc[1][1] += a1 * bq.y;
            acc[1][2] += a1 * bq.z; acc[1][3] += a1 * bq.w;
        }

        if (c + 1 < NCHUNK)
            sts_tiles(As[buf ^ 1], Bs[buf ^ 1], tid, ra, rb);
        __syncthreads();
    }

    // --- fused LSTM epilogue
    const int hcol = h0 + hc;
    const float bi = b_ih[hcol]            + b_hh[hcol];
    const float bf = b_ih[Hdim + hcol]     + b_hh[Hdim + hcol];
    const float bg = b_ih[2 * Hdim + hcol] + b_hh[2 * Hdim + hcol];
    const float bo = b_ih[3 * Hdim + hcol] + b_hh[3 * Hdim + hcol];

#pragma unroll
    for (int r = 0; r < 2; r++) {
        int b = b0 + r0 + r;
        const float* cx = g_ctx + (size_t)b * 3 * Hdim;
        float iv = sigmoidf(acc[r][0] + bi) * cx[hcol];
        float fv = sigmoidf(acc[r][1] + bf) * cx[Hdim + hcol];
        float gv = tanhf(acc[r][2] + bg);
        float ov = sigmoidf(acc[r][3] + bo) * cx[2 * Hdim + hcol];
        float cc = fv * g_c[b * Hdim + hcol] + iv * gv;
        g_c[b * Hdim + hcol] = cc;
        h_out[b * Hdim + hcol] = ov * tanhf(cc);
    }
}

// ---------------------------------------------------------------------------
// VAE head. Final h lives in g_h[0] ((127+1)&1 = 0).
// out layout: recon_x [256*128] | mu [256*16] | log_var [256*16]
// ---------------------------------------------------------------------------
__global__ __launch_bounds__(128) void head_kernel(
    const float* __restrict__ eps,     // [256,16]
    const float* __restrict__ mu_w,    // [512,16]
    const float* __restrict__ mu_b,    // [16]
    const float* __restrict__ lv_w,    // [512,16]
    const float* __restrict__ lv_b,    // [16]
    const float* __restrict__ dec_w1,  // [16,512]
    const float* __restrict__ dec_b1,  // [512]
    const float* __restrict__ dec_w2,  // [512,128]
    const float* __restrict__ dec_b2,  // [128]
    float* __restrict__ out)
{
    __shared__ float hrow[Hdim];
    __shared__ float zv[Ldim];
    __shared__ float d1[Hdim];
    int b = blockIdx.x;
    const float* h = g_h[0] + (size_t)b * Hdim;

    for (int k = threadIdx.x; k < Hdim; k += 128) hrow[k] = h[k];
    __syncthreads();

    if (threadIdx.x < Ldim) {
        int j = threadIdx.x;
        float m = mu_b[j];
        for (int k = 0; k < Hdim; k++) m += hrow[k] * mu_w[k * Ldim + j];
        out[Bsz * Fdim + b * Ldim + j] = m;  // mu
        float lv = lv_b[j];
        for (int k = 0; k < Hdim; k++) lv += hrow[k] * lv_w[k * Ldim + j];
        out[Bsz * Fdim + Bsz * Ldim + b * Ldim + j] = lv;  // log_var
        zv[j] = m + eps[b * Ldim + j] * expf(0.5f * lv);
    }
    __syncthreads();

    for (int n = threadIdx.x; n < Hdim; n += 128) {
        float s = dec_b1[n];
#pragma unroll
        for (int k = 0; k < Ldim; k++) s += zv[k] * dec_w1[k * Hdim + n];
        d1[n] = fmaxf(s, 0.0f);
    }
    __syncthreads();

    {
        int n = threadIdx.x;  // 0..127
        float s = dec_b2[n];
        for (int k = 0; k < Hdim; k++) s += d1[k] * dec_w2[k * Fdim + n];
        out[(size_t)b * Fdim + n] = s;  // recon_x
    }
}

// ---------------------------------------------------------------------------
extern "C" void kernel_launch(void* const* d_in, const int* in_sizes, int n_in,
                              void* d_out, int out_size)
{
    const float* x       = (const float*)d_in[0];
    const float* context = (const float*)d_in[1];
    const float* eps     = (const float*)d_in[2];
    const float* W_ih    = (const float*)d_in[3];
    const float* b_ih    = (const float*)d_in[4];
    const float* W_hh    = (const float*)d_in[5];
    const float* b_hh    = (const float*)d_in[6];
    const float* cg_w1   = (const float*)d_in[7];
    const float* cg_b1   = (const float*)d_in[8];
    const float* cg_w2   = (const float*)d_in[9];
    const float* cg_b2   = (const float*)d_in[10];
    const float* mu_w    = (const float*)d_in[11];
    const float* mu_b    = (const float*)d_in[12];
    const float* lv_w    = (const float*)d_in[13];
    const float* lv_b    = (const float*)d_in[14];
    const float* dec_w1  = (const float*)d_in[15];
    const float* dec_b1  = (const float*)d_in[16];
    const float* dec_w2  = (const float*)d_in[17];
    const float* dec_b2  = (const float*)d_in[18];
    float* out = (float*)d_out;

    zero_state_kernel<<<(Bsz * Hdim + 255) / 256, 256>>>();
    ctx1_kernel<<<Bsz, 128>>>(context, cg_w1, cg_b1);
    ctx2_kernel<<<Bsz, 256>>>(cg_w2, cg_b2);

    dim3 sgrid(Hdim / 16, Bsz / 16);   // (32, 16) = 512 CTAs
    for (int t = 0; t < Slen; t++) {
        step_kernel<<<sgrid, 128>>>(x, W_ih, b_ih, W_hh, b_hh, t);
    }

    head_kernel<<<Bsz, 128>>>(eps, mu_w, mu_b, lv_w, lv_b,
                              dec_w1, dec_b1, dec_w2, dec_b2, out);
}

// round 4
// speedup vs baseline: 1.0013x; 1.0013x over previous
#include <cuda_runtime.h>
#include <math.h>

// Problem dims
#define Bsz 256
#define Slen 128
#define Fdim 128
#define Hdim 512
#define Cdim 64
#define Ldim 16
#define G4  2048           // 4*H
#define KTOT 640           // H + F (fused [h | x_t] GEMM)
#define NCHUNK 20          // 640 / 32

#define APAD 19            // A smem row pad (conflict-free transposing STS)
#define BPAD 72            // B smem row pad

// Scratch (device globals; no allocations allowed)
__device__ float g_h[2][Bsz * Hdim];     // ping-pong hidden state
__device__ float g_c[Bsz * Hdim];        // cell state
__device__ float g_tmp[Bsz * Hdim];      // context-gate hidden
__device__ float g_ctx[Bsz * 3 * Hdim];  // sigmoid context gates [ci|cf|co]

__device__ __forceinline__ float sigmoidf(float x) {
    return 1.0f / (1.0f + expf(-x));
}

// ---------------------------------------------------------------------------
__global__ void zero_state_kernel() {
    int i = blockIdx.x * blockDim.x + threadIdx.x;
    if (i < Bsz * Hdim) {
        g_h[0][i] = 0.0f;
        g_c[i] = 0.0f;
    }
}

// ---------------------------------------------------------------------------
// Context gate stage 1: tmp = relu(context @ cg_w1 + cg_b1)   [256,512]
// ---------------------------------------------------------------------------
__global__ __launch_bounds__(128) void ctx1_kernel(
    const float* __restrict__ context,   // [256,64]
    const float* __restrict__ cg_w1,     // [64,512]
    const float* __restrict__ cg_b1)     // [512]
{
    __shared__ float cr[Cdim];
    int b = blockIdx.x;
    for (int k = threadIdx.x; k < Cdim; k += 128) cr[k] = context[b * Cdim + k];
    __syncthreads();
#pragma unroll
    for (int j = 0; j < 4; j++) {
        int n = threadIdx.x + j * 128;
        float s = cg_b1[n];
        for (int k = 0; k < Cdim; k++) s += cr[k] * cg_w1[k * Hdim + n];
        g_tmp[b * Hdim + n] = fmaxf(s, 0.0f);
    }
}

// ---------------------------------------------------------------------------
// Context gate stage 2: ctx = sigmoid(tmp @ cg_w2 + cg_b2)    [256,1536]
// ---------------------------------------------------------------------------
__global__ __launch_bounds__(256) void ctx2_kernel(
    const float* __restrict__ cg_w2,     // [512,1536]
    const float* __restrict__ cg_b2)     // [1536]
{
    __shared__ float tr[Hdim];
    int b = blockIdx.x;
    for (int k = threadIdx.x; k < Hdim; k += 256) tr[k] = g_tmp[b * Hdim + k];
    __syncthreads();
#pragma unroll
    for (int j = 0; j < 6; j++) {
        int n = threadIdx.x + j * 256;
        float s = cg_b2[n];
        for (int k = 0; k < Hdim; k++) s += tr[k] * cg_w2[k * 3 * Hdim + n];
        g_ctx[b * 3 * Hdim + n] = sigmoidf(s);
    }
}

// ---------------------------------------------------------------------------
// Fused LSTM step. CTA tile: 16 batch x (16 hcol x 4 gates). grid (32,16)=512.
// 128 threads; thread = 2 rows x 4 gates = 8 accumulators.
// K=640 in 20 chunks of 32, double-buffered smem, register-staged prefetch.
// A smem: [kk][row] pad APAD (conflict-free both sides).
// B smem: [kk][hc*4+g] pad BPAD (LDS.128 per thread yields 4 gate weights).
// ---------------------------------------------------------------------------
__device__ __forceinline__ void ldg_tiles(
    const float* __restrict__ h_in, const float* __restrict__ x,
    const float* __restrict__ W_hh, const float* __restrict__ W_ih,
    int t, int b0, int h0, int k0, int tid, float4& ra, float4 rb[4])
{
    // A: 16 rows x 32 kk = 128 float4; lane: q = tid&7 (k-quad), r = tid>>3 (row)
    const int q = tid & 7;
    const int r = tid >> 3;
    if (k0 < Hdim) {
        ra = *(const float4*)&h_in[(b0 + r) * Hdim + k0 + q * 4];
#pragma unroll
        for (int i = 0; i < 4; i++) {
            int idx = i * 128 + tid, kk = idx >> 4, f = idx & 15;
            int g = f >> 2, hq = f & 3;
            rb[i] = *(const float4*)&W_hh[(k0 + kk) * G4 + g * Hdim + h0 + hq * 4];
        }
    } else {
        int kx = k0 - Hdim;
        ra = *(const float4*)&x[((size_t)(b0 + r) * Slen + t) * Fdim + kx + q * 4];
#pragma unroll
        for (int i = 0; i < 4; i++) {
            int idx = i * 128 + tid, kk = idx >> 4, f = idx & 15;
            int g = f >> 2, hq = f & 3;
            rb[i] = *(const float4*)&W_ih[(kx + kk) * G4 + g * Hdim + h0 + hq * 4];
        }
    }
}

__device__ __forceinline__ void sts_tiles(
    float (*__restrict__ As)[APAD], float* __restrict__ Bs,
    int tid, const float4& ra, const float4 rb[4])
{
    const int q = tid & 7;
    const int r = tid >> 3;
    As[q * 4 + 0][r] = ra.x;
    As[q * 4 + 1][r] = ra.y;
    As[q * 4 + 2][r] = ra.z;
    As[q * 4 + 3][r] = ra.w;
#pragma unroll
    for (int i = 0; i < 4; i++) {
        int idx = i * 128 + tid, kk = idx >> 4, f = idx & 15;
        int g = f >> 2, hq = f & 3;
        float* brow = Bs + kk * BPAD;
        brow[(hq * 4 + 0) * 4 + g] = rb[i].x;
        brow[(hq * 4 + 1) * 4 + g] = rb[i].y;
        brow[(hq * 4 + 2) * 4 + g] = rb[i].z;
        brow[(hq * 4 + 3) * 4 + g] = rb[i].w;
    }
}

__global__ __launch_bounds__(128) void step_kernel(
    const float* __restrict__ x,      // [256,128,128]
    const float* __restrict__ W_ih,   // [128,2048]
    const float* __restrict__ b_ih,   // [2048]
    const float* __restrict__ W_hh,   // [512,2048]
    const float* __restrict__ b_hh,   // [2048]
    int t)
{
    __shared__ float As[2][32][APAD];
    __shared__ float Bs[2][32 * BPAD];

    const int tid = threadIdx.x;
    const int hc = tid & 15;          // h-column within tile
    const int r0 = (tid >> 4) * 2;    // 2 batch rows per thread
    const int h0 = blockIdx.x * 16;
    const int b0 = blockIdx.y * 16;

    const float* __restrict__ h_in = g_h[t & 1];
    float* __restrict__ h_out = g_h[(t + 1) & 1];

    float acc[2][4];
#pragma unroll
    for (int r = 0; r < 2; r++)
#pragma unroll
        for (int g = 0; g < 4; g++) acc[r][g] = 0.0f;

    float4 ra, rb[4];
    ldg_tiles(h_in, x, W_hh, W_ih, t, b0, h0, 0, tid, ra, rb);
    sts_tiles(As[0], Bs[0], tid, ra, rb);
    __syncthreads();

    for (int c = 0; c < NCHUNK; c++) {
        const int buf = c & 1;
        if (c + 1 < NCHUNK)
            ldg_tiles(h_in, x, W_hh, W_ih, t, b0, h0, (c + 1) * 32, tid, ra, rb);

        const float (*__restrict__ Asb)[APAD] = As[buf];
        const float* __restrict__ Bsb = Bs[buf];
#pragma unroll
        for (int kk = 0; kk < 32; kk++) {
            float4 bq = *(const float4*)&Bsb[kk * BPAD + hc * 4];
            float a0 = Asb[kk][r0 + 0];
            float a1 = Asb[kk][r0 + 1];
            acc[0][0] += a0 * bq.x; acc[0][1] += a0 * bq.y;
            acc[0][2] += a0 * bq.z; acc[0][3] += a0 * bq.w;
            acc[1][0] += a1 * bq.x; acc[1][1] += a1 * bq.y;
            acc[1][2] += a1 * bq.z; acc[1][3] += a1 * bq.w;
        }

        if (c + 1 < NCHUNK)
            sts_tiles(As[buf ^ 1], Bs[buf ^ 1], tid, ra, rb);
        __syncthreads();
    }

    // --- fused LSTM epilogue
    const int hcol = h0 + hc;
    const float bi = b_ih[hcol]            + b_hh[hcol];
    const float bf = b_ih[Hdim + hcol]     + b_hh[Hdim + hcol];
    const float bg = b_ih[2 * Hdim + hcol] + b_hh[2 * Hdim + hcol];
    const float bo = b_ih[3 * Hdim + hcol] + b_hh[3 * Hdim + hcol];

#pragma unroll
    for (int r = 0; r < 2; r++) {
        int b = b0 + r0 + r;
        const float* cx = g_ctx + (size_t)b * 3 * Hdim;
        float iv = sigmoidf(acc[r][0] + bi) * cx[hcol];
        float fv = sigmoidf(acc[r][1] + bf) * cx[Hdim + hcol];
        float gv = tanhf(acc[r][2] + bg);
        float ov = sigmoidf(acc[r][3] + bo) * cx[2 * Hdim + hcol];
        float cc = fv * g_c[b * Hdim + hcol] + iv * gv;
        g_c[b * Hdim + hcol] = cc;
        h_out[b * Hdim + hcol] = ov * tanhf(cc);
    }
}

// ---------------------------------------------------------------------------
// VAE head. Final h lives in g_h[0] ((127+1)&1 = 0).
// out layout: recon_x [256*128] | mu [256*16] | log_var [256*16]
// ---------------------------------------------------------------------------
__global__ __launch_bounds__(128) void head_kernel(
    const float* __restrict__ eps,     // [256,16]
    const float* __restrict__ mu_w,    // [512,16]
    const float* __restrict__ mu_b,    // [16]
    const float* __restrict__ lv_w,    // [512,16]
    const float* __restrict__ lv_b,    // [16]
    const float* __restrict__ dec_w1,  // [16,512]
    const float* __restrict__ dec_b1,  // [512]
    const float* __restrict__ dec_w2,  // [512,128]
    const float* __restrict__ dec_b2,  // [128]
    float* __restrict__ out)
{
    __shared__ float hrow[Hdim];
    __shared__ float zv[Ldim];
    __shared__ float d1[Hdim];
    int b = blockIdx.x;
    const float* h = g_h[0] + (size_t)b * Hdim;

    for (int k = threadIdx.x; k < Hdim; k += 128) hrow[k] = h[k];
    __syncthreads();

    if (threadIdx.x < Ldim) {
        int j = threadIdx.x;
        float m = mu_b[j];
        for (int k = 0; k < Hdim; k++) m += hrow[k] * mu_w[k * Ldim + j];
        out[Bsz * Fdim + b * Ldim + j] = m;  // mu
        float lv = lv_b[j];
        for (int k = 0; k < Hdim; k++) lv += hrow[k] * lv_w[k * Ldim + j];
        out[Bsz * Fdim + Bsz * Ldim + b * Ldim + j] = lv;  // log_var
        zv[j] = m + eps[b * Ldim + j] * expf(0.5f * lv);
    }
    __syncthreads();

    for (int n = threadIdx.x; n < Hdim; n += 128) {
        float s = dec_b1[n];
#pragma unroll
        for (int k = 0; k < Ldim; k++) s += zv[k] * dec_w1[k * Hdim + n];
        d1[n] = fmaxf(s, 0.0f);
    }
    __syncthreads();

    {
        int n = threadIdx.x;  // 0..127
        float s = dec_b2[n];
        for (int k = 0; k < Hdim; k++) s += d1[k] * dec_w2[k * Fdim + n];
        out[(size_t)b * Fdim + n] = s;  // recon_x
    }
}

// ---------------------------------------------------------------------------
extern "C" void kernel_launch(void* const* d_in, const int* in_sizes, int n_in,
                              void* d_out, int out_size)
{
    const float* x       = (const float*)d_in[0];
    const float* context = (const float*)d_in[1];
    const float* eps     = (const float*)d_in[2];
    const float* W_ih    = (const float*)d_in[3];
    const float* b_ih    = (const float*)d_in[4];
    const float* W_hh    = (const float*)d_in[5];
    const float* b_hh    = (const float*)d_in[6];
    const float* cg_w1   = (const float*)d_in[7];
    const float* cg_b1   = (const float*)d_in[8];
    const float* cg_w2   = (const float*)d_in[9];
    const float* cg_b2   = (const float*)d_in[10];
    const float* mu_w    = (const float*)d_in[11];
    const float* mu_b    = (const float*)d_in[12];
    const float* lv_w    = (const float*)d_in[13];
    const float* lv_b    = (const float*)d_in[14];
    const float* dec_w1  = (const float*)d_in[15];
    const float* dec_b1  = (const float*)d_in[16];
    const float* dec_w2  = (const float*)d_in[17];
    const float* dec_b2  = (const float*)d_in[18];
    float* out = (float*)d_out;

    zero_state_kernel<<<(Bsz * Hdim + 255) / 256, 256>>>();
    ctx1_kernel<<<Bsz, 128>>>(context, cg_w1, cg_b1);
    ctx2_kernel<<<Bsz, 256>>>(cg_w2, cg_b2);

    dim3 sgrid(Hdim / 16, Bsz / 16);   // (32, 16) = 512 CTAs
    for (int t = 0; t < Slen; t++) {
        step_kernel<<<sgrid, 128>>>(x, W_ih, b_ih, W_hh, b_hh, t);
    }

    head_kernel<<<Bsz, 128>>>(eps, mu_w, mu_b, lv_w, lv_b,
                              dec_w1, dec_b1, dec_w2, dec_b2, out);
}

// round 6
// speedup vs baseline: 3.6085x; 3.6038x over previous
#include <cuda_runtime.h>
#include <cuda_bf16.h>
#include <math.h>
#include <stdint.h>

#define Bsz 256
#define Slen 128
#define Fdim 128
#define Hdim 512
#define Cdim 64
#define Ldim 16
#define KTOT 640
#define NCH 10            // K chunks of 64

#define MT 64             // CTA batch tile
#define NT 64             // CTA gate-col tile
#define ROWB 144          // smem row stride bytes (64 bf16 = 128B + 16B pad)
#define ATILE (64 * ROWB) // 9216 B (one half: hi or lo)
#define BTILE (64 * ROWB)
#define BUFBYTES (2 * ATILE + 2 * BTILE)   // 36864
#define NBUF 3
#define SMEM_TOTAL (NBUF * BUFBYTES)       // 110592
#define CST 68            // epilogue C row stride (floats)

// -------- device globals (no runtime allocation allowed) --------
__device__ __align__(16) __nv_bfloat16 g_Wh[2048 * KTOT];  // W^T, n'=hcol*4+gate
__device__ __align__(16) __nv_bfloat16 g_Wl[2048 * KTOT];
__device__ __align__(16) __nv_bfloat16 g_xh[Bsz * Slen * Fdim];
__device__ __align__(16) __nv_bfloat16 g_xl[Bsz * Slen * Fdim];
__device__ __align__(16) __nv_bfloat16 g_hh[2][Bsz * Hdim];
__device__ __align__(16) __nv_bfloat16 g_hl[2][Bsz * Hdim];
__device__ float g_c[Bsz * Hdim];
__device__ __align__(16) float g_bsum[2048];
__device__ float g_tmp[Bsz * Hdim];
__device__ float g_ctx[Bsz * 3 * Hdim];

__device__ __forceinline__ uint32_t smem_u32(const void* p) {
    uint32_t a;
    asm("{ .reg .u64 t; cvta.to.shared.u64 t, %1; cvt.u32.u64 %0, t; }" : "=r"(a) : "l"(p));
    return a;
}

__device__ __forceinline__ void cp16(uint32_t sdst, const void* gsrc) {
    asm volatile("cp.async.cg.shared.global [%0], [%1], 16;" :: "r"(sdst), "l"(gsrc));
}
#define CP_COMMIT() asm volatile("cp.async.commit_group;" ::: "memory")
#define CP_WAIT(n)  asm volatile("cp.async.wait_group %0;" :: "n"(n) : "memory")

__device__ __forceinline__ void mma16816(float c[4], const uint32_t a[4], const uint32_t b[2]) {
    asm volatile(
        "mma.sync.aligned.m16n8k16.row.col.f32.bf16.bf16.f32 "
        "{%0,%1,%2,%3}, {%4,%5,%6,%7}, {%8,%9}, {%0,%1,%2,%3};"
        : "+f"(c[0]), "+f"(c[1]), "+f"(c[2]), "+f"(c[3])
        : "r"(a[0]), "r"(a[1]), "r"(a[2]), "r"(a[3]), "r"(b[0]), "r"(b[1]));
}

__device__ __forceinline__ float sigf(float x) {
    return __fdividef(1.0f, 1.0f + __expf(-x));
}
__device__ __forceinline__ float tanh_fast(float x) {
    float xc = fminf(fmaxf(x, -15.0f), 15.0f);
    float e = __expf(2.0f * xc);
    return __fdividef(e - 1.0f, e + 1.0f);
}

// ------------------------- prep kernels -------------------------
__global__ __launch_bounds__(256) void zero_state_kernel() {
    int i = blockIdx.x * 256 + threadIdx.x;
    if (i < Bsz * Hdim) {
        g_c[i] = 0.0f;
        g_hh[0][i] = __float2bfloat16(0.0f);
        g_hl[0][i] = __float2bfloat16(0.0f);
    }
}

__global__ __launch_bounds__(256) void split_w_kernel(
    const float* __restrict__ W_ih, const float* __restrict__ W_hh)
{
    int idx = blockIdx.x * 256 + threadIdx.x;
    if (idx >= 2048 * KTOT) return;
    int np = idx / KTOT, k = idx - np * KTOT;
    int n = (np & 3) * Hdim + (np >> 2);
    float v = (k < Hdim) ? W_hh[k * 2048 + n] : W_ih[(k - Hdim) * 2048 + n];
    __nv_bfloat16 hi = __float2bfloat16(v);
    g_Wh[idx] = hi;
    g_Wl[idx] = __float2bfloat16(v - __bfloat162float(hi));
}

__global__ __launch_bounds__(256) void split_x_kernel(const float* __restrict__ x) {
    int i = blockIdx.x * 256 + threadIdx.x;
    if (i >= Bsz * Slen * Fdim) return;
    float v = x[i];
    __nv_bfloat16 hi = __float2bfloat16(v);
    g_xh[i] = hi;
    g_xl[i] = __float2bfloat16(v - __bfloat162float(hi));
}

__global__ __launch_bounds__(256) void bias_kernel(
    const float* __restrict__ b_ih, const float* __restrict__ b_hh)
{
    int np = blockIdx.x * 256 + threadIdx.x;
    if (np >= 2048) return;
    int n = (np & 3) * Hdim + (np >> 2);
    g_bsum[np] = b_ih[n] + b_hh[n];
}

__global__ __launch_bounds__(128) void ctx1_kernel(
    const float* __restrict__ context, const float* __restrict__ cg_w1,
    const float* __restrict__ cg_b1)
{
    __shared__ float cr[Cdim];
    int b = blockIdx.x;
    for (int k = threadIdx.x; k < Cdim; k += 128) cr[k] = context[b * Cdim + k];
    __syncthreads();
#pragma unroll
    for (int j = 0; j < 4; j++) {
        int n = threadIdx.x + j * 128;
        float s = cg_b1[n];
        for (int k = 0; k < Cdim; k++) s += cr[k] * cg_w1[k * Hdim + n];
        g_tmp[b * Hdim + n] = fmaxf(s, 0.0f);
    }
}

__global__ __launch_bounds__(256) void ctx2_kernel(
    const float* __restrict__ cg_w2, const float* __restrict__ cg_b2)
{
    __shared__ float tr[Hdim];
    int b = blockIdx.x;
    for (int k = threadIdx.x; k < Hdim; k += 256) tr[k] = g_tmp[b * Hdim + k];
    __syncthreads();
#pragma unroll
    for (int j = 0; j < 6; j++) {
        int n = threadIdx.x + j * 256;
        float s = cg_b2[n];
        for (int k = 0; k < Hdim; k++) s += tr[k] * cg_w2[k * 3 * Hdim + n];
        g_ctx[b * 3 * Hdim + n] = 1.0f / (1.0f + expf(-s));
    }
}

// ------------------- HMMA (mma.sync) LSTM step -------------------
// grid (32, 4): x = N'-tile (64 gate cols = 16 hcol x 4 gates), y = 64 batch.
// 256 threads = 8 warps (4 M x 2 N); warp tile M16 x N32.
// gates = [h|x_t] @ Wcat via 3-term bf16-split mma, fp32 accum.
__global__ __launch_bounds__(256) void step_kernel(int t)
{
    extern __shared__ char smem[];
    const uint32_t sb = smem_u32(smem);
    const int tid = threadIdx.x;
    const int wid = tid >> 5, lane = tid & 31;
    const int wm = wid & 3, wn = wid >> 2;
    const int gID = lane >> 2, tid4 = lane & 3;
    const int n0 = blockIdx.x * NT;
    const int hcol0 = blockIdx.x * (NT / 4);
    const int b0 = blockIdx.y * MT;

    const __nv_bfloat16* __restrict__ hh = g_hh[t & 1];
    const __nv_bfloat16* __restrict__ hl = g_hl[t & 1];
    __nv_bfloat16* __restrict__ ohh = g_hh[(t + 1) & 1];
    __nv_bfloat16* __restrict__ ohl = g_hl[(t + 1) & 1];

    float acc[4][4];
#pragma unroll
    for (int j = 0; j < 4; j++)
#pragma unroll
        for (int r = 0; r < 4; r++) acc[j][r] = 0.0f;

    auto copy_chunk = [&](int c) {
        const uint32_t base = sb + (uint32_t)(c % NBUF) * BUFBYTES;
        // A = [h | x_t]: hi/lo, 64 rows x 64 halves
#pragma unroll
        for (int hlf = 0; hlf < 2; hlf++) {
#pragma unroll
            for (int i = 0; i < 2; i++) {
                int idx = i * 256 + tid;          // 0..511
                int r = idx >> 3, q = idx & 7;
                uint32_t dst = base + hlf * ATILE + r * ROWB + q * 16;
                if (c < 8) {
                    const __nv_bfloat16* src = hlf ? hl : hh;
                    cp16(dst, src + (size_t)(b0 + r) * Hdim + c * 64 + q * 8);
                } else {
                    const __nv_bfloat16* src = hlf ? g_xl : g_xh;
                    cp16(dst, src + ((size_t)(b0 + r) * Slen + t) * Fdim + (c - 8) * 64 + q * 8);
                }
            }
        }
        // B = W^T rows n0..n0+63
#pragma unroll
        for (int hlf = 0; hlf < 2; hlf++) {
#pragma unroll
            for (int i = 0; i < 2; i++) {
                int idx = i * 256 + tid;
                int r = idx >> 3, q = idx & 7;
                uint32_t dst = base + 2 * ATILE + hlf * BTILE + r * ROWB + q * 16;
                const __nv_bfloat16* src = hlf ? g_Wl : g_Wh;
                cp16(dst, src + (size_t)(n0 + r) * KTOT + c * 64 + q * 8);
            }
        }
    };

    auto compute_chunk = [&](int buf) {
        const char* base = smem + (size_t)buf * BUFBYTES;
        const char* Ab = base;
        const char* Bb = base + 2 * ATILE;
#pragma unroll
        for (int ks = 0; ks < 4; ks++) {
            const int kb = ks * 32 + tid4 * 4;    // byte offset in row
            uint32_t ah[4], al[4];
            const char* ar = Ab + (wm * 16 + gID) * ROWB + kb;
            ah[0] = *(const uint32_t*)(ar);
            ah[2] = *(const uint32_t*)(ar + 16);
            ah[1] = *(const uint32_t*)(ar + 8 * ROWB);
            ah[3] = *(const uint32_t*)(ar + 8 * ROWB + 16);
            const char* arl = ar + ATILE;
            al[0] = *(const uint32_t*)(arl);
            al[2] = *(const uint32_t*)(arl + 16);
            al[1] = *(const uint32_t*)(arl + 8 * ROWB);
            al[3] = *(const uint32_t*)(arl + 8 * ROWB + 16);
#pragma unroll
            for (int j = 0; j < 4; j++) {
                const char* br = Bb + (wn * 32 + j * 8 + gID) * ROWB + kb;
                uint32_t bh[2], bl[2];
                bh[0] = *(const uint32_t*)(br);
                bh[1] = *(const uint32_t*)(br + 16);
                bl[0] = *(const uint32_t*)(br + BTILE);
                bl[1] = *(const uint32_t*)(br + BTILE + 16);
                mma16816(acc[j], ah, bh);
                mma16816(acc[j], ah, bl);
                mma16816(acc[j], al, bh);
            }
        }
    };

    copy_chunk(0); CP_COMMIT();
    copy_chunk(1); CP_COMMIT();

    for (int c = 0; c < NCH; c++) {
        if (c + 2 < NCH) { copy_chunk(c + 2); CP_COMMIT(); }
        if (c + 2 < NCH)      { CP_WAIT(2); }
        else if (c + 1 < NCH) { CP_WAIT(1); }
        else                  { CP_WAIT(0); }
        __syncthreads();
        compute_chunk(c % NBUF);
        __syncthreads();
    }

    // ---- epilogue: accumulators -> smem -> fused LSTM update ----
    float* Csm = (float*)smem;   // 64 x CST floats (reuses tile buffers)
#pragma unroll
    for (int j = 0; j < 4; j++) {
        int n = wn * 32 + j * 8 + tid4 * 2;
        int m0r = wm * 16 + gID;
        *(float2*)&Csm[m0r * CST + n]       = make_float2(acc[j][0], acc[j][1]);
        *(float2*)&Csm[(m0r + 8) * CST + n] = make_float2(acc[j][2], acc[j][3]);
    }
    __syncthreads();

#pragma unroll
    for (int it = 0; it < 4; it++) {
        int idx = it * 256 + tid;
        int m = idx >> 4, hcl = idx & 15;
        float4 gv = *(float4*)&Csm[m * CST + hcl * 4];
        float4 bb = *(const float4*)&g_bsum[n0 + hcl * 4];
        int b = b0 + m;
        int hc = hcol0 + hcl;
        const float* cxp = g_ctx + (size_t)b * (3 * Hdim);
        float iv = sigf(gv.x + bb.x) * cxp[hc];
        float fv = sigf(gv.y + bb.y) * cxp[Hdim + hc];
        float gg = tanh_fast(gv.z + bb.z);
        float ov = sigf(gv.w + bb.w) * cxp[2 * Hdim + hc];
        float cn = fv * g_c[(size_t)b * Hdim + hc] + iv * gg;
        g_c[(size_t)b * Hdim + hc] = cn;
        float hv = ov * tanh_fast(cn);
        __nv_bfloat16 hhi = __float2bfloat16(hv);
        ohh[(size_t)b * Hdim + hc] = hhi;
        ohl[(size_t)b * Hdim + hc] = __float2bfloat16(hv - __bfloat162float(hhi));
    }
}

// ------------------------- VAE head -------------------------
__global__ __launch_bounds__(128) void head_kernel(
    const float* __restrict__ eps,
    const float* __restrict__ mu_w, const float* __restrict__ mu_b,
    const float* __restrict__ lv_w, const float* __restrict__ lv_b,
    const float* __restrict__ dec_w1, const float* __restrict__ dec_b1,
    const float* __restrict__ dec_w2, const float* __restrict__ dec_b2,
    float* __restrict__ out)
{
    __shared__ float hrow[Hdim];
    __shared__ float zv[Ldim];
    __shared__ float d1[Hdim];
    int b = blockIdx.x;

    for (int k = threadIdx.x; k < Hdim; k += 128)
        hrow[k] = __bfloat162float(g_hh[0][(size_t)b * Hdim + k]) +
                  __bfloat162float(g_hl[0][(size_t)b * Hdim + k]);
    __syncthreads();

    if (threadIdx.x < Ldim) {
        int j = threadIdx.x;
        float m = mu_b[j];
        for (int k = 0; k < Hdim; k++) m += hrow[k] * mu_w[k * Ldim + j];
        out[Bsz * Fdim + b * Ldim + j] = m;
        float lv = lv_b[j];
        for (int k = 0; k < Hdim; k++) lv += hrow[k] * lv_w[k * Ldim + j];
        out[Bsz * Fdim + Bsz * Ldim + b * Ldim + j] = lv;
        zv[j] = m + eps[b * Ldim + j] * expf(0.5f * lv);
    }
    __syncthreads();

    for (int n = threadIdx.x; n < Hdim; n += 128) {
        float s = dec_b1[n];
#pragma unroll
        for (int k = 0; k < Ldim; k++) s += zv[k] * dec_w1[k * Hdim + n];
        d1[n] = fmaxf(s, 0.0f);
    }
    __syncthreads();

    {
        int n = threadIdx.x;
        float s = dec_b2[n];
        for (int k = 0; k < Hdim; k++) s += d1[k] * dec_w2[k * Fdim + n];
        out[(size_t)b * Fdim + n] = s;
    }
}

// ---------------------------------------------------------------------------
extern "C" void kernel_launch(void* const* d_in, const int* in_sizes, int n_in,
                              void* d_out, int out_size)
{
    const float* x       = (const float*)d_in[0];
    const float* context = (const float*)d_in[1];
    const float* eps     = (const float*)d_in[2];
    const float* W_ih    = (const float*)d_in[3];
    const float* b_ih    = (const float*)d_in[4];
    const float* W_hh    = (const float*)d_in[5];
    const float* b_hh    = (const float*)d_in[6];
    const float* cg_w1   = (const float*)d_in[7];
    const float* cg_b1   = (const float*)d_in[8];
    const float* cg_w2   = (const float*)d_in[9];
    const float* cg_b2   = (const float*)d_in[10];
    const float* mu_w    = (const float*)d_in[11];
    const float* mu_b    = (const float*)d_in[12];
    const float* lv_w    = (const float*)d_in[13];
    const float* lv_b    = (const float*)d_in[14];
    const float* dec_w1  = (const float*)d_in[15];
    const float* dec_b1  = (const float*)d_in[16];
    const float* dec_w2  = (const float*)d_in[17];
    const float* dec_b2  = (const float*)d_in[18];
    float* out = (float*)d_out;

    cudaFuncSetAttribute(step_kernel, cudaFuncAttributeMaxDynamicSharedMemorySize,
                         SMEM_TOTAL);

    zero_state_kernel<<<(Bsz * Hdim + 255) / 256, 256>>>();
    split_w_kernel<<<(2048 * KTOT + 255) / 256, 256>>>(W_ih, W_hh);
    split_x_kernel<<<(Bsz * Slen * Fdim + 255) / 256, 256>>>(x);
    bias_kernel<<<8, 256>>>(b_ih, b_hh);
    ctx1_kernel<<<Bsz, 128>>>(context, cg_w1, cg_b1);
    ctx2_kernel<<<Bsz, 256>>>(cg_w2, cg_b2);

    dim3 sgrid(2048 / NT, Bsz / MT);   // (32, 4)
    for (int t = 0; t < Slen; t++) {
        step_kernel<<<sgrid, 256, SMEM_TOTAL>>>(t);
    }

    head_kernel<<<Bsz, 128>>>(eps, mu_w, mu_b, lv_w, lv_b,
                              dec_w1, dec_b1, dec_w2, dec_b2, out);
}